// round 15
// baseline (speedup 1.0000x reference)
#include <cuda_runtime.h>
#include <cuda_bf16.h>
#include <cuda_fp16.h>
#include <cstdint>

#define BATCH 2
#define CCH   512
#define NH    8
#define DH    64
#define SEQ   4096
#define BH    (BATCH * NH)
#define MROWS (BATCH * SEQ)    // 8192

// ---- device-global scratch (all fp16) ----
__device__ __align__(16) __half g_tokf[(size_t)MROWS * CCH];
__device__ __align__(16) __half g_Wf[(size_t)4 * CCH * CCH];          // q,k,v,p
__device__ __align__(16) __half g_Qf[(size_t)BH * SEQ * DH];          // pre-scaled log2e/8
__device__ __align__(16) __half g_Kf[(size_t)BH * SEQ * DH];
__device__ __align__(16) __half g_Vf[(size_t)BH * SEQ * DH];
__device__ __align__(16) __half g_Of[(size_t)MROWS * CCH];            // attn out [b*s, c]

// ---- PTX helpers (baseline ISA, valid on compute_103) ----
__device__ __forceinline__ uint32_t smem_u32(const void* p) {
    uint32_t a;
    asm("{ .reg .u64 t; cvta.to.shared.u64 t, %1; cvt.u32.u64 %0, t; }" : "=r"(a) : "l"(p));
    return a;
}
__device__ __forceinline__ void cpasync16(uint32_t dst, const void* src) {
    asm volatile("cp.async.cg.shared.global [%0], [%1], 16;" :: "r"(dst), "l"(src));
}
#define CP_COMMIT() asm volatile("cp.async.commit_group;" ::: "memory")
#define CP_WAIT0()  asm volatile("cp.async.wait_group 0;" ::: "memory")
#define CP_WAIT1()  asm volatile("cp.async.wait_group 1;" ::: "memory")

__device__ __forceinline__ void ldsm4(uint32_t* r, uint32_t a) {
    asm volatile("ldmatrix.sync.aligned.m8n8.x4.shared.b16 {%0,%1,%2,%3}, [%4];"
        : "=r"(r[0]), "=r"(r[1]), "=r"(r[2]), "=r"(r[3]) : "r"(a));
}
__device__ __forceinline__ void ldsm4t(uint32_t* r, uint32_t a) {
    asm volatile("ldmatrix.sync.aligned.m8n8.x4.trans.shared.b16 {%0,%1,%2,%3}, [%4];"
        : "=r"(r[0]), "=r"(r[1]), "=r"(r[2]), "=r"(r[3]) : "r"(a));
}
__device__ __forceinline__ void mma16816h(float* d, const uint32_t* a, const uint32_t* b) {
    asm volatile("mma.sync.aligned.m16n8k16.row.col.f32.f16.f16.f32 "
        "{%0,%1,%2,%3}, {%4,%5,%6,%7}, {%8,%9}, {%0,%1,%2,%3};"
        : "+f"(d[0]), "+f"(d[1]), "+f"(d[2]), "+f"(d[3])
        : "r"(a[0]), "r"(a[1]), "r"(a[2]), "r"(a[3]), "r"(b[0]), "r"(b[1]));
}
__device__ __forceinline__ uint32_t ex2_h2(uint32_t x) {
    uint32_t r;
    asm("ex2.approx.f16x2 %0, %1;" : "=r"(r) : "r"(x));
    return r;
}
__device__ __forceinline__ uint32_t hadd2(uint32_t a, uint32_t b) {
    uint32_t r;
    asm("add.f16x2 %0, %1, %2;" : "=r"(r) : "r"(a), "r"(b));
    return r;
}

#define SWZ(off) ((off) ^ (((off) >> 3) & 0x70))

__device__ __forceinline__ uint32_t pack_h2(float x, float y) {
    __half2 h = __floats2half2_rn(x, y);
    return *(uint32_t*)&h;
}

// ---------------------------------------------------------------------------
// Prep A: W matrices -> fp16.
// ---------------------------------------------------------------------------
__global__ __launch_bounds__(256) void wconv_kernel(
    const float* __restrict__ Wq, const float* __restrict__ Wk,
    const float* __restrict__ Wv, const float* __restrict__ Wp)
{
    const int idx = blockIdx.x * 256 + threadIdx.x;
    if (idx >= 4 * CCH * CCH) return;
    const int which = idx >> 18, local = idx & 262143;
    const float* W = (which == 0) ? Wq : (which == 1) ? Wk : (which == 2) ? Wv : Wp;
    g_Wf[idx] = __float2half_rn(W[local]);
}

// ---------------------------------------------------------------------------
// Prep B: transpose x[b][c][s] -> tok fp16 [b*s][c]. 32x32 tiles.
// ---------------------------------------------------------------------------
__global__ __launch_bounds__(256) void xprep_kernel(const float* __restrict__ x)
{
    __shared__ float tile[32][33];
    const int b = blockIdx.z;
    const int s0 = blockIdx.x * 32, c0 = blockIdx.y * 32;
    const int tx = threadIdx.x & 31, ty = threadIdx.x >> 5;   // 32 x 8
#pragma unroll
    for (int i = 0; i < 4; i++)
        tile[ty + 8 * i][tx] = x[((size_t)(b * CCH + c0 + ty + 8 * i)) * SEQ + s0 + tx];
    __syncthreads();
#pragma unroll
    for (int i = 0; i < 4; i++) {
        size_t o = ((size_t)(b * SEQ + s0 + ty + 8 * i)) * CCH + c0 + tx;
        g_tokf[o] = __float2half_rn(tile[tx][ty + 8 * i]);
    }
}

// ---------------------------------------------------------------------------
// FUSED QKV GEMM: one CTA computes Q,K,V tiles (A loaded once, 3 B tiles).
// C_z[128 x 64] = A[128 x 512] * Wz[64 x 512]^T, z = 0,1,2.
// 256 threads, 8 warps (4m x 2n). Stage 40KB (A 16K + 3 x B 8K), 2 stages.
// ---------------------------------------------------------------------------
#define QSTG 40960
#define QSMEM (2 * QSTG)   // 81920

__device__ __forceinline__ void qkv3_load_tile(uint32_t smb, int stg,
                                               size_t m0g, int n0, int chk)
{
    const int tid = threadIdx.x;
    const uint32_t base = smb + stg * QSTG;
#pragma unroll
    for (int t = 0; t < 4; t++) {                 // A: 128 rows x 8 chunks
        int idx = tid + t * 256;
        int row = idx >> 3, u = idx & 7;
        uint32_t off = SWZ((uint32_t)(row * 128 + u * 16));
        cpasync16(base + off, g_tokf + (m0g + row) * CCH + chk * 64 + u * 8);
    }
#pragma unroll
    for (int z = 0; z < 3; z++) {                 // B_z: 64 rows x 8 chunks
#pragma unroll
        for (int t = 0; t < 2; t++) {
            int idx = tid + t * 256;
            int row = idx >> 3, u = idx & 7;
            uint32_t off = SWZ((uint32_t)(row * 128 + u * 16));
            cpasync16(base + 16384 + z * 8192 + off,
                      g_Wf + (size_t)z * CCH * CCH + (size_t)(n0 + row) * CCH + chk * 64 + u * 8);
        }
    }
    CP_COMMIT();
}

__global__ __launch_bounds__(256) void gemm_qkv3(
    const float* __restrict__ bq, const float* __restrict__ bk, const float* __restrict__ bv)
{
    extern __shared__ __align__(1024) char sm_q[];
    const uint32_t smb = smem_u32(sm_q);
    const size_t m0g = (size_t)blockIdx.x * 128;
    const int n0 = blockIdx.y * 64;
    const int lane = threadIdx.x & 31, warp = threadIdx.x >> 5;
    const int wm = (warp & 3) * 32, wn = (warp >> 2) * 32;

    float C[3][2][4][4];
#pragma unroll
    for (int z = 0; z < 3; z++)
#pragma unroll
        for (int tm = 0; tm < 2; tm++)
#pragma unroll
            for (int j = 0; j < 4; j++)
#pragma unroll
                for (int c = 0; c < 4; c++) C[z][tm][j][c] = 0.f;

    const int arow = (lane & 7) + ((lane & 8) ? 8 : 0);
    const int acb  = (lane & 16) ? 16 : 0;
    const int brow = (lane & 7) + ((lane & 16) ? 8 : 0);
    const int bcb  = (lane & 8) ? 16 : 0;

    qkv3_load_tile(smb, 0, m0g, n0, 0);

    for (int chk = 0; chk < CCH / 64; chk++) {
        if (chk + 1 < CCH / 64) {
            qkv3_load_tile(smb, (chk + 1) & 1, m0g, n0, chk + 1);
            CP_WAIT1();
        } else {
            CP_WAIT0();
        }
        __syncthreads();

        const uint32_t base = smb + (chk & 1) * QSTG;
#pragma unroll
        for (int k = 0; k < 4; k++) {
            uint32_t af[2][4];
#pragma unroll
            for (int tm = 0; tm < 2; tm++)
                ldsm4(af[tm], base + SWZ((uint32_t)((wm + tm * 16 + arow) * 128 + k * 32 + acb)));
#pragma unroll
            for (int z = 0; z < 3; z++) {
                uint32_t bf[2][4];
#pragma unroll
                for (int half = 0; half < 2; half++)
                    ldsm4(bf[half], base + 16384 + z * 8192 +
                          SWZ((uint32_t)((wn + half * 16 + brow) * 128 + k * 32 + bcb)));
#pragma unroll
                for (int tm = 0; tm < 2; tm++)
#pragma unroll
                    for (int half = 0; half < 2; half++) {
                        mma16816h(C[z][tm][2 * half],     af[tm], bf[half]);
                        mma16816h(C[z][tm][2 * half + 1], af[tm], bf[half] + 2);
                    }
            }
        }
        __syncthreads();
    }

    const int b = (int)(m0g >> 12);
    const int s_base = (int)(m0g & 4095);
    const int h = n0 >> 6;
    const size_t bhead = (size_t)b * NH + h;

#pragma unroll
    for (int z = 0; z < 3; z++) {
        const float* bias = (z == 0) ? bq : (z == 1) ? bk : bv;
        const float scale = (z == 0) ? 0.18033688011112042f : 1.0f;   // log2(e)/8
        __half* of = (z == 0) ? g_Qf : (z == 1) ? g_Kf : g_Vf;
#pragma unroll
        for (int tm = 0; tm < 2; tm++) {
            int r = wm + tm * 16 + (lane >> 2);
#pragma unroll
            for (int j = 0; j < 4; j++) {
                int col = wn + j * 8 + 2 * (lane & 3);
                float b0 = bias[n0 + col], b1 = bias[n0 + col + 1];
                size_t o0 = (bhead * SEQ + s_base + r) * DH + col;
                *(uint32_t*)(of + o0) = pack_h2((C[z][tm][j][0] + b0) * scale,
                                                (C[z][tm][j][1] + b1) * scale);
                *(uint32_t*)(of + o0 + (size_t)8 * DH) =
                    pack_h2((C[z][tm][j][2] + b0) * scale,
                            (C[z][tm][j][3] + b1) * scale);
            }
        }
    }
}

// ---------------------------------------------------------------------------
// GEMM 2 (unchanged): output projection -> [b][c][s] fp32 via smem bounce.
// ---------------------------------------------------------------------------
#define GSTG 24576

__device__ __forceinline__ void proj_load_tile(uint32_t smb, int stg,
                                               size_t m0g, int n0, int chk)
{
    const int tid = threadIdx.x;
    const uint32_t base = smb + stg * GSTG;
#pragma unroll
    for (int t = 0; t < 4; t++) {
        int idx = tid + t * 256;
        int row = idx >> 3, u = idx & 7;
        uint32_t off = SWZ((uint32_t)(row * 128 + u * 16));
        cpasync16(base + off, g_Of + (m0g + row) * CCH + chk * 64 + u * 8);
    }
#pragma unroll
    for (int t = 0; t < 2; t++) {
        int idx = tid + t * 256;
        int row = idx >> 3, u = idx & 7;
        uint32_t off = SWZ((uint32_t)(row * 128 + u * 16));
        cpasync16(base + 16384 + off,
                  g_Wf + (size_t)3 * CCH * CCH + (size_t)(n0 + row) * CCH + chk * 64 + u * 8);
    }
    CP_COMMIT();
}

__global__ __launch_bounds__(256) void gemm_proj(
    const float* __restrict__ bp, float* __restrict__ out)
{
    __shared__ __align__(1024) char sm_p[2 * GSTG];
    const uint32_t smb = smem_u32(sm_p);
    const size_t m0g = (size_t)blockIdx.x * 128;
    const int n0 = blockIdx.y * 64;
    const int tid = threadIdx.x, lane = tid & 31, warp = tid >> 5;
    const int wm = (warp & 3) * 32, wn = (warp >> 2) * 32;

    float C[2][4][4];
#pragma unroll
    for (int tm = 0; tm < 2; tm++)
#pragma unroll
        for (int j = 0; j < 4; j++)
#pragma unroll
            for (int c = 0; c < 4; c++) C[tm][j][c] = 0.f;

    const int arow = (lane & 7) + ((lane & 8) ? 8 : 0);
    const int acb  = (lane & 16) ? 16 : 0;
    const int brow = (lane & 7) + ((lane & 16) ? 8 : 0);
    const int bcb  = (lane & 8) ? 16 : 0;

    proj_load_tile(smb, 0, m0g, n0, 0);

    for (int chk = 0; chk < CCH / 64; chk++) {
        if (chk + 1 < CCH / 64) {
            proj_load_tile(smb, (chk + 1) & 1, m0g, n0, chk + 1);
            CP_WAIT1();
        } else {
            CP_WAIT0();
        }
        __syncthreads();

        const uint32_t base = smb + (chk & 1) * GSTG;
#pragma unroll
        for (int k = 0; k < 4; k++) {
            uint32_t af[2][4];
#pragma unroll
            for (int tm = 0; tm < 2; tm++)
                ldsm4(af[tm], base + SWZ((uint32_t)((wm + tm * 16 + arow) * 128 + k * 32 + acb)));
            uint32_t bf[2][4];
#pragma unroll
            for (int half = 0; half < 2; half++)
                ldsm4(bf[half], base + 16384 + SWZ((uint32_t)((wn + half * 16 + brow) * 128 + k * 32 + bcb)));
#pragma unroll
            for (int tm = 0; tm < 2; tm++)
#pragma unroll
                for (int half = 0; half < 2; half++) {
                    mma16816h(C[tm][2 * half],     af[tm], bf[half]);
                    mma16816h(C[tm][2 * half + 1], af[tm], bf[half] + 2);
                }
        }
        __syncthreads();
    }

    float (*Cs)[128] = (float(*)[128])sm_p;

    __syncthreads();
#pragma unroll
    for (int tm = 0; tm < 2; tm++) {
        int r = wm + tm * 16 + (lane >> 2);
#pragma unroll
        for (int j = 0; j < 4; j++) {
            int col = wn + j * 8 + 2 * (lane & 3);
            Cs[col][r]         = C[tm][j][0];
            Cs[col + 1][r]     = C[tm][j][1];
            Cs[col][r + 8]     = C[tm][j][2];
            Cs[col + 1][r + 8] = C[tm][j][3];
        }
    }
    __syncthreads();

    const int b = (int)(m0g >> 12);
    const int s_base = (int)(m0g & 4095);
#pragma unroll
    for (int t = 0; t < 8; t++) {
        int idx = tid + t * 256;
        int n = idx >> 5, v = idx & 31;
        float bb = bp[n0 + n];
        float4 c = *(float4*)&Cs[n][v * 4];
        c.x += bb; c.y += bb; c.z += bb; c.w += bb;
        *(float4*)(out + ((size_t)(b * CCH + n0 + n)) * SEQ + s_base + v * 4) = c;
    }
}

// ---------------------------------------------------------------------------
// Flash attention (R11 version, proven 169us): fp16 single-term, exp2
// softmax, 32 rows/warp + KV-split. Static smem 40KB: Q 8KB @0;
// stage s @ 8192 + s*16384. Epilogue reduces O across kv halves via smem.
// ---------------------------------------------------------------------------
__device__ __forceinline__ void flash_load_kv(uint32_t smb, int bh, int it, int stg)
{
    const int tid = threadIdx.x;
    const uint32_t base = smb + 8192 + stg * 16384;
#pragma unroll
    for (int k = 0; k < 4; k++) {
        int idx = tid + k * 128;
        int row = idx >> 3, u = idx & 7;
        uint32_t off = SWZ((uint32_t)(row * 128 + u * 16));
        size_t g = ((size_t)bh * SEQ + it * 64 + row) * DH + u * 8;
        cpasync16(base + off,        g_Kf + g);
        cpasync16(base + 8192 + off, g_Vf + g);
    }
    CP_COMMIT();
}

__global__ __launch_bounds__(128) void flash_mma()
{
    __shared__ __align__(1024) char sm_f[40960];
    const uint32_t smb = smem_u32(sm_f);
    const int tid  = threadIdx.x;
    const int lane = tid & 31, warp = tid >> 5;
    const int rg = warp & 1, ch = warp >> 1;
    const int bh = blockIdx.y;
    const int s0 = blockIdx.x * 64;
    const int m0 = rg * 32;
    const int chb = ch * 32;

    // prologue: Q + KV stage 0
#pragma unroll
    for (int k = 0; k < 4; k++) {
        int idx = tid + k * 128;
        int row = idx >> 3, u = idx & 7;
        uint32_t off = SWZ((uint32_t)(row * 128 + u * 16));
        cpasync16(smb + off, g_Qf + ((size_t)bh * SEQ + s0 + row) * DH + u * 8);
    }
    flash_load_kv(smb, bh, 0, 0);
    CP_WAIT0();
    __syncthreads();

    // Q fragments: 2 m-tiles (32 rows)
    uint32_t qf[2][4][4];
    {
        int cb = (lane & 16) ? 16 : 0;
#pragma unroll
        for (int mt = 0; mt < 2; mt++) {
            int row = m0 + mt * 16 + (lane & 7) + ((lane & 8) ? 8 : 0);
#pragma unroll
            for (int k = 0; k < 4; k++)
                ldsm4(qf[mt][k], smb + SWZ((uint32_t)(row * 128 + k * 32 + cb)));
        }
    }

    float O[2][8][4];
#pragma unroll
    for (int mt = 0; mt < 2; mt++)
#pragma unroll
        for (int j = 0; j < 8; j++)
#pragma unroll
            for (int c = 0; c < 4; c++) O[mt][j][c] = 0.f;
    float ls[2][2] = {{0.f, 0.f}, {0.f, 0.f}};

    const int krow = (lane & 7) + ((lane & 16) ? 8 : 0);
    const int kcb  = (lane & 8) ? 16 : 0;
    const int vrow = (lane & 7) + ((lane & 8) ? 8 : 0);
    const int vcb  = (lane & 16) ? 16 : 0;

    for (int it = 0; it < SEQ / 64; it++) {
        const int cur = it & 1;
        if (it + 1 < SEQ / 64) {
            flash_load_kv(smb, bh, it + 1, cur ^ 1);
            CP_WAIT1();
        } else {
            CP_WAIT0();
        }
        __syncthreads();

        const uint32_t kb = smb + 8192 + cur * 16384;

        // S[32 rows x 32 kv] = Q K^T (log2 domain)
        float S[2][4][4];
#pragma unroll
        for (int mt = 0; mt < 2; mt++)
#pragma unroll
            for (int j = 0; j < 4; j++)
#pragma unroll
                for (int c = 0; c < 4; c++) S[mt][j][c] = 0.f;

#pragma unroll
        for (int k = 0; k < 4; k++) {
            uint32_t kf[2][4];
#pragma unroll
            for (int nt = 0; nt < 2; nt++)
                ldsm4(kf[nt], kb + SWZ((uint32_t)((chb + nt * 16 + krow) * 128 + k * 32 + kcb)));
#pragma unroll
            for (int mt = 0; mt < 2; mt++)
#pragma unroll
                for (int nt = 0; nt < 2; nt++) {
                    mma16816h(S[mt][2 * nt],     qf[mt][k], kf[nt]);
                    mma16816h(S[mt][2 * nt + 1], qf[mt][k], kf[nt] + 2);
                }
        }

        // P = 2^S via ex2.f16x2; row-sum partials in f16x2
        uint32_t pf[2][2][4];
#pragma unroll
        for (int mt = 0; mt < 2; mt++) {
#pragma unroll
            for (int ks = 0; ks < 2; ks++) {
                pf[mt][ks][0] = ex2_h2(pack_h2(S[mt][2 * ks][0],     S[mt][2 * ks][1]));
                pf[mt][ks][1] = ex2_h2(pack_h2(S[mt][2 * ks][2],     S[mt][2 * ks][3]));
                pf[mt][ks][2] = ex2_h2(pack_h2(S[mt][2 * ks + 1][0], S[mt][2 * ks + 1][1]));
                pf[mt][ks][3] = ex2_h2(pack_h2(S[mt][2 * ks + 1][2], S[mt][2 * ks + 1][3]));
            }
            uint32_t h0 = hadd2(hadd2(pf[mt][0][0], pf[mt][0][2]),
                                hadd2(pf[mt][1][0], pf[mt][1][2]));
            uint32_t h1 = hadd2(hadd2(pf[mt][0][1], pf[mt][0][3]),
                                hadd2(pf[mt][1][1], pf[mt][1][3]));
            float2 f0 = __half22float2(*(__half2*)&h0);
            float2 f1 = __half22float2(*(__half2*)&h1);
            ls[mt][0] += f0.x + f0.y;
            ls[mt][1] += f1.x + f1.y;
        }

        // O += P V (partial over this warp's kv half)
#pragma unroll
        for (int ks = 0; ks < 2; ks++) {
#pragma unroll
            for (int p = 0; p < 4; p++) {
                uint32_t vf[4];
                ldsm4t(vf, kb + 8192 + SWZ((uint32_t)((chb + ks * 16 + vrow) * 128 + p * 32 + vcb)));
#pragma unroll
                for (int mt = 0; mt < 2; mt++) {
                    mma16816h(O[mt][2 * p],     pf[mt][ks], vf);
                    mma16816h(O[mt][2 * p + 1], pf[mt][ks], vf + 2);
                }
            }
        }
        __syncthreads();
    }

    // ---- epilogue: reduce O/lsum across kv halves (ch), normalize, store ----
#pragma unroll
    for (int mt = 0; mt < 2; mt++)
#pragma unroll
        for (int hh = 0; hh < 2; hh++) {
            ls[mt][hh] += __shfl_xor_sync(0xffffffffu, ls[mt][hh], 1);
            ls[mt][hh] += __shfl_xor_sync(0xffffffffu, ls[mt][hh], 2);
        }

    float* Ls = (float*)sm_f;              // [64]
    float* Os = (float*)(sm_f + 1024);     // [64][68] fp32 = 17408B

    if (ch == 1) {
        if ((lane & 3) == 0) {
#pragma unroll
            for (int mt = 0; mt < 2; mt++) {
                Ls[m0 + mt * 16 + (lane >> 2)]     = ls[mt][0];
                Ls[m0 + mt * 16 + (lane >> 2) + 8] = ls[mt][1];
            }
        }
#pragma unroll
        for (int mt = 0; mt < 2; mt++) {
            int r = m0 + mt * 16 + (lane >> 2);
#pragma unroll
            for (int j = 0; j < 8; j++) {
                int col = j * 8 + 2 * (lane & 3);
                *(float2*)&Os[r * 68 + col]       = make_float2(O[mt][j][0], O[mt][j][1]);
                *(float2*)&Os[(r + 8) * 68 + col] = make_float2(O[mt][j][2], O[mt][j][3]);
            }
        }
    }
    __syncthreads();

    if (ch == 0) {
        const int b = bh >> 3, h = bh & 7;
#pragma unroll
        for (int mt = 0; mt < 2; mt++) {
            int r = m0 + mt * 16 + (lane >> 2);
            float i0 = 1.f / (ls[mt][0] + Ls[r]);
            float i1 = 1.f / (ls[mt][1] + Ls[r + 8]);
            size_t base0 = ((size_t)(b * SEQ + s0 + r)) * CCH + h * DH + 2 * (lane & 3);
            size_t base1 = base0 + (size_t)8 * CCH;
#pragma unroll
            for (int j = 0; j < 8; j++) {
                int col = j * 8 + 2 * (lane & 3);
                float2 a0 = *(float2*)&Os[r * 68 + col];
                float2 a1 = *(float2*)&Os[(r + 8) * 68 + col];
                *(uint32_t*)(g_Of + base0 + 8 * j) =
                    pack_h2((O[mt][j][0] + a0.x) * i0, (O[mt][j][1] + a0.y) * i0);
                *(uint32_t*)(g_Of + base1 + 8 * j) =
                    pack_h2((O[mt][j][2] + a1.x) * i1, (O[mt][j][3] + a1.y) * i1);
            }
        }
    }
}

// ---------------------------------------------------------------------------
extern "C" void kernel_launch(void* const* d_in, const int* in_sizes, int n_in,
                              void* d_out, int out_size)
{
    const float* x  = (const float*)d_in[0];
    const float* Wq = (const float*)d_in[1];
    const float* bq = (const float*)d_in[2];
    const float* Wk = (const float*)d_in[3];
    const float* bk = (const float*)d_in[4];
    const float* Wv = (const float*)d_in[5];
    const float* bv = (const float*)d_in[6];
    const float* Wp = (const float*)d_in[7];
    const float* bp = (const float*)d_in[8];
    float* out = (float*)d_out;

    static bool attr_done = false;
    if (!attr_done) {
        cudaFuncSetAttribute(gemm_qkv3, cudaFuncAttributeMaxDynamicSharedMemorySize, QSMEM);
        attr_done = true;
    }

    wconv_kernel<<<4096, 256>>>(Wq, Wk, Wv, Wp);
    xprep_kernel<<<dim3(SEQ / 32, CCH / 32, BATCH), 256>>>(x);
    gemm_qkv3<<<dim3(MROWS / 128, CCH / 64), 256, QSMEM>>>(bq, bk, bv);
    flash_mma<<<dim3(SEQ / 64, BH), 128>>>();
    gemm_proj<<<dim3(MROWS / 128, CCH / 64), 256>>>(bp, out);
}

// round 16
// speedup vs baseline: 1.0317x; 1.0317x over previous
#include <cuda_runtime.h>
#include <cuda_bf16.h>
#include <cuda_fp16.h>
#include <cstdint>

#define BATCH 2
#define CCH   512
#define NH    8
#define DH    64
#define SEQ   4096
#define BH    (BATCH * NH)
#define MROWS (BATCH * SEQ)    // 8192

// ---- device-global scratch (all fp16) ----
__device__ __align__(16) __half g_tokf[(size_t)MROWS * CCH];
__device__ __align__(16) __half g_Wf[(size_t)4 * CCH * CCH];          // q,k,v,p
__device__ __align__(16) __half g_Qf[(size_t)BH * SEQ * DH];          // pre-scaled log2e/8
__device__ __align__(16) __half g_Kf[(size_t)BH * SEQ * DH];
__device__ __align__(16) __half g_Vf[(size_t)BH * SEQ * DH];
__device__ __align__(16) __half g_Of[(size_t)MROWS * CCH];            // attn out [b*s, c]

// ---- PTX helpers (baseline ISA, valid on compute_103) ----
__device__ __forceinline__ uint32_t smem_u32(const void* p) {
    uint32_t a;
    asm("{ .reg .u64 t; cvta.to.shared.u64 t, %1; cvt.u32.u64 %0, t; }" : "=r"(a) : "l"(p));
    return a;
}
__device__ __forceinline__ void cpasync16(uint32_t dst, const void* src) {
    asm volatile("cp.async.cg.shared.global [%0], [%1], 16;" :: "r"(dst), "l"(src));
}
#define CP_COMMIT() asm volatile("cp.async.commit_group;" ::: "memory")
#define CP_WAIT0()  asm volatile("cp.async.wait_group 0;" ::: "memory")
#define CP_WAIT1()  asm volatile("cp.async.wait_group 1;" ::: "memory")

__device__ __forceinline__ void ldsm4(uint32_t* r, uint32_t a) {
    asm volatile("ldmatrix.sync.aligned.m8n8.x4.shared.b16 {%0,%1,%2,%3}, [%4];"
        : "=r"(r[0]), "=r"(r[1]), "=r"(r[2]), "=r"(r[3]) : "r"(a));
}
__device__ __forceinline__ void ldsm4t(uint32_t* r, uint32_t a) {
    asm volatile("ldmatrix.sync.aligned.m8n8.x4.trans.shared.b16 {%0,%1,%2,%3}, [%4];"
        : "=r"(r[0]), "=r"(r[1]), "=r"(r[2]), "=r"(r[3]) : "r"(a));
}
__device__ __forceinline__ void mma16816h(float* d, const uint32_t* a, const uint32_t* b) {
    asm volatile("mma.sync.aligned.m16n8k16.row.col.f32.f16.f16.f32 "
        "{%0,%1,%2,%3}, {%4,%5,%6,%7}, {%8,%9}, {%0,%1,%2,%3};"
        : "+f"(d[0]), "+f"(d[1]), "+f"(d[2]), "+f"(d[3])
        : "r"(a[0]), "r"(a[1]), "r"(a[2]), "r"(a[3]), "r"(b[0]), "r"(b[1]));
}
__device__ __forceinline__ uint32_t ex2_h2(uint32_t x) {
    uint32_t r;
    asm("ex2.approx.f16x2 %0, %1;" : "=r"(r) : "r"(x));
    return r;
}
__device__ __forceinline__ uint32_t hadd2(uint32_t a, uint32_t b) {
    uint32_t r;
    asm("add.f16x2 %0, %1, %2;" : "=r"(r) : "r"(a), "r"(b));
    return r;
}

#define SWZ(off) ((off) ^ (((off) >> 3) & 0x70))

__device__ __forceinline__ uint32_t pack_h2(float x, float y) {
    __half2 h = __floats2half2_rn(x, y);
    return *(uint32_t*)&h;
}

// ---------------------------------------------------------------------------
// Fused prep: blocks [0,4096) convert W -> fp16; blocks [4096,8192) transpose
// x[b][c][s] -> tok fp16 [b*s][c] (32x32 tiles). One launch, one wave.
// ---------------------------------------------------------------------------
__global__ __launch_bounds__(256) void prep_kernel(
    const float* __restrict__ Wq, const float* __restrict__ Wk,
    const float* __restrict__ Wv, const float* __restrict__ Wp,
    const float* __restrict__ x)
{
    __shared__ float tile[32][33];
    if (blockIdx.x < 4096) {
        const int idx = blockIdx.x * 256 + threadIdx.x;
        const int which = idx >> 18, local = idx & 262143;
        const float* W = (which == 0) ? Wq : (which == 1) ? Wk : (which == 2) ? Wv : Wp;
        g_Wf[idx] = __float2half_rn(W[local]);
    } else {
        const int bid = blockIdx.x - 4096;       // 128 x 16 x 2 decode
        const int s0 = (bid & 127) * 32;
        const int c0 = ((bid >> 7) & 15) * 32;
        const int b  = bid >> 11;
        const int tx = threadIdx.x & 31, ty = threadIdx.x >> 5;   // 32 x 8
#pragma unroll
        for (int i = 0; i < 4; i++)
            tile[ty + 8 * i][tx] = x[((size_t)(b * CCH + c0 + ty + 8 * i)) * SEQ + s0 + tx];
        __syncthreads();
#pragma unroll
        for (int i = 0; i < 4; i++) {
            size_t o = ((size_t)(b * SEQ + s0 + ty + 8 * i)) * CCH + c0 + tx;
            g_tokf[o] = __float2half_rn(tile[tx][ty + 8 * i]);
        }
    }
}

// ---------------------------------------------------------------------------
// Shared GEMM mainloop, fp16 single-term, 2-stage double-buffered.
// C[128 x 64] = A[128 x 512] * B[64 x 512]^T. 256 threads, 8 warps (4m x 2n).
// ---------------------------------------------------------------------------
#define GSTG 24576

struct GemmAcc { float C[2][4][4]; };

__device__ __forceinline__ void gemm_load_tile(
    uint32_t smb, int stg,
    const __half* Af, size_t m0g, const __half* Bf, int n0, int ch)
{
    const int tid = threadIdx.x;
    const uint32_t base = smb + stg * GSTG;
#pragma unroll
    for (int t = 0; t < 4; t++) {
        int idx = tid + t * 256;
        int row = idx >> 3, u = idx & 7;
        uint32_t off = SWZ((uint32_t)(row * 128 + u * 16));
        cpasync16(base + off, Af + (m0g + row) * CCH + ch * 64 + u * 8);
    }
#pragma unroll
    for (int t = 0; t < 2; t++) {
        int idx = tid + t * 256;
        int row = idx >> 3, u = idx & 7;
        uint32_t off = SWZ((uint32_t)(row * 128 + u * 16));
        cpasync16(base + 16384 + off, Bf + (size_t)(n0 + row) * CCH + ch * 64 + u * 8);
    }
    CP_COMMIT();
}

__device__ __forceinline__ void gemm_mainloop(
    GemmAcc& acc, uint32_t smb,
    const __half* Af, size_t m0g, const __half* Bf, int n0)
{
    const int lane = threadIdx.x & 31, warp = threadIdx.x >> 5;
    const int wm = (warp & 3) * 32, wn = (warp >> 2) * 32;

#pragma unroll
    for (int tm = 0; tm < 2; tm++)
#pragma unroll
        for (int j = 0; j < 4; j++)
#pragma unroll
            for (int c = 0; c < 4; c++) acc.C[tm][j][c] = 0.f;

    const int arow = (lane & 7) + ((lane & 8) ? 8 : 0);
    const int acb  = (lane & 16) ? 16 : 0;
    const int brow = (lane & 7) + ((lane & 16) ? 8 : 0);
    const int bcb  = (lane & 8) ? 16 : 0;

    gemm_load_tile(smb, 0, Af, m0g, Bf, n0, 0);

    for (int ch = 0; ch < CCH / 64; ch++) {
        if (ch + 1 < CCH / 64) {
            gemm_load_tile(smb, (ch + 1) & 1, Af, m0g, Bf, n0, ch + 1);
            CP_WAIT1();
        } else {
            CP_WAIT0();
        }
        __syncthreads();

        const uint32_t base = smb + (ch & 1) * GSTG;
#pragma unroll
        for (int k = 0; k < 4; k++) {
            uint32_t af[2][4];
#pragma unroll
            for (int tm = 0; tm < 2; tm++)
                ldsm4(af[tm], base + SWZ((uint32_t)((wm + tm * 16 + arow) * 128 + k * 32 + acb)));
            uint32_t bf[2][4];
#pragma unroll
            for (int half = 0; half < 2; half++)
                ldsm4(bf[half], base + 16384 + SWZ((uint32_t)((wn + half * 16 + brow) * 128 + k * 32 + bcb)));
#pragma unroll
            for (int tm = 0; tm < 2; tm++)
#pragma unroll
                for (int half = 0; half < 2; half++) {
                    mma16816h(acc.C[tm][2 * half],     af[tm], bf[half]);
                    mma16816h(acc.C[tm][2 * half + 1], af[tm], bf[half] + 2);
                }
        }
        __syncthreads();
    }
}

// ---------------------------------------------------------------------------
// GEMM 1: QKV projection -> fp16 [bh][s][d]. Q pre-scaled by log2(e)/8.
// ---------------------------------------------------------------------------
__global__ __launch_bounds__(256) void gemm_qkv(
    const float* __restrict__ bq, const float* __restrict__ bk, const float* __restrict__ bv)
{
    __shared__ __align__(1024) char sm_q[2 * GSTG];
    const uint32_t smb = smem_u32(sm_q);
    const int z = blockIdx.z;
    const size_t m0g = (size_t)blockIdx.x * 128;
    const int n0 = blockIdx.y * 64;
    const float* bias = (z == 0) ? bq : (z == 1) ? bk : bv;
    const float scale = (z == 0) ? 0.18033688011112042f : 1.0f;   // log2(e)/8
    __half* of = (z == 0) ? g_Qf : (z == 1) ? g_Kf : g_Vf;

    GemmAcc acc;
    gemm_mainloop(acc, smb, g_tokf, m0g, g_Wf + (size_t)z * CCH * CCH, n0);

    const int lane = threadIdx.x & 31, warp = threadIdx.x >> 5;
    const int wm = (warp & 3) * 32, wn = (warp >> 2) * 32;
    const int b = (int)(m0g >> 12);
    const int s_base = (int)(m0g & 4095);
    const int h = n0 >> 6;
    const size_t bhead = (size_t)b * NH + h;

#pragma unroll
    for (int tm = 0; tm < 2; tm++) {
        int r = wm + tm * 16 + (lane >> 2);
#pragma unroll
        for (int j = 0; j < 4; j++) {
            int col = wn + j * 8 + 2 * (lane & 3);
            float b0 = bias[n0 + col], b1 = bias[n0 + col + 1];
            size_t o0 = (bhead * SEQ + s_base + r) * DH + col;
            *(uint32_t*)(of + o0) = pack_h2((acc.C[tm][j][0] + b0) * scale,
                                            (acc.C[tm][j][1] + b1) * scale);
            *(uint32_t*)(of + o0 + (size_t)8 * DH) = pack_h2((acc.C[tm][j][2] + b0) * scale,
                                                             (acc.C[tm][j][3] + b1) * scale);
        }
    }
}

// ---------------------------------------------------------------------------
// GEMM 2: output projection -> [b][c][s] fp32 via smem bounce.
// ---------------------------------------------------------------------------
__global__ __launch_bounds__(256) void gemm_proj(
    const float* __restrict__ bp, float* __restrict__ out)
{
    __shared__ __align__(1024) char sm_p[2 * GSTG];
    const uint32_t smb = smem_u32(sm_p);
    const size_t m0g = (size_t)blockIdx.x * 128;
    const int n0 = blockIdx.y * 64;

    GemmAcc acc;
    gemm_mainloop(acc, smb, g_Of, m0g, g_Wf + (size_t)3 * CCH * CCH, n0);

    const int tid = threadIdx.x, lane = tid & 31, warp = tid >> 5;
    const int wm = (warp & 3) * 32, wn = (warp >> 2) * 32;
    float (*Cs)[128] = (float(*)[128])sm_p;

    __syncthreads();
#pragma unroll
    for (int tm = 0; tm < 2; tm++) {
        int r = wm + tm * 16 + (lane >> 2);
#pragma unroll
        for (int j = 0; j < 4; j++) {
            int col = wn + j * 8 + 2 * (lane & 3);
            Cs[col][r]         = acc.C[tm][j][0];
            Cs[col + 1][r]     = acc.C[tm][j][1];
            Cs[col][r + 8]     = acc.C[tm][j][2];
            Cs[col + 1][r + 8] = acc.C[tm][j][3];
        }
    }
    __syncthreads();

    const int b = (int)(m0g >> 12);
    const int s_base = (int)(m0g & 4095);
#pragma unroll
    for (int t = 0; t < 8; t++) {
        int idx = tid + t * 256;
        int n = idx >> 5, v = idx & 31;
        float bb = bp[n0 + n];
        float4 c = *(float4*)&Cs[n][v * 4];
        c.x += bb; c.y += bb; c.z += bb; c.w += bb;
        *(float4*)(out + ((size_t)(b * CCH + n0 + n)) * SEQ + s_base + v * 4) = c;
    }
}

// ---------------------------------------------------------------------------
// Flash attention (R11, proven 169us): fp16 single-term, exp2 softmax,
// 32 rows/warp + KV-split. Static smem 40KB: Q 8KB @0; stages @8192+s*16384.
// Epilogue reduces O across kv halves via smem.
// ---------------------------------------------------------------------------
__device__ __forceinline__ void flash_load_kv(uint32_t smb, int bh, int it, int stg)
{
    const int tid = threadIdx.x;
    const uint32_t base = smb + 8192 + stg * 16384;
#pragma unroll
    for (int k = 0; k < 4; k++) {
        int idx = tid + k * 128;
        int row = idx >> 3, u = idx & 7;
        uint32_t off = SWZ((uint32_t)(row * 128 + u * 16));
        size_t g = ((size_t)bh * SEQ + it * 64 + row) * DH + u * 8;
        cpasync16(base + off,        g_Kf + g);
        cpasync16(base + 8192 + off, g_Vf + g);
    }
    CP_COMMIT();
}

__global__ __launch_bounds__(128) void flash_mma()
{
    __shared__ __align__(1024) char sm_f[40960];
    const uint32_t smb = smem_u32(sm_f);
    const int tid  = threadIdx.x;
    const int lane = tid & 31, warp = tid >> 5;
    const int rg = warp & 1, ch = warp >> 1;
    const int bh = blockIdx.y;
    const int s0 = blockIdx.x * 64;
    const int m0 = rg * 32;
    const int chb = ch * 32;

    // prologue: Q + KV stage 0
#pragma unroll
    for (int k = 0; k < 4; k++) {
        int idx = tid + k * 128;
        int row = idx >> 3, u = idx & 7;
        uint32_t off = SWZ((uint32_t)(row * 128 + u * 16));
        cpasync16(smb + off, g_Qf + ((size_t)bh * SEQ + s0 + row) * DH + u * 8);
    }
    flash_load_kv(smb, bh, 0, 0);
    CP_WAIT0();
    __syncthreads();

    // Q fragments: 2 m-tiles (32 rows)
    uint32_t qf[2][4][4];
    {
        int cb = (lane & 16) ? 16 : 0;
#pragma unroll
        for (int mt = 0; mt < 2; mt++) {
            int row = m0 + mt * 16 + (lane & 7) + ((lane & 8) ? 8 : 0);
#pragma unroll
            for (int k = 0; k < 4; k++)
                ldsm4(qf[mt][k], smb + SWZ((uint32_t)(row * 128 + k * 32 + cb)));
        }
    }

    float O[2][8][4];
#pragma unroll
    for (int mt = 0; mt < 2; mt++)
#pragma unroll
        for (int j = 0; j < 8; j++)
#pragma unroll
            for (int c = 0; c < 4; c++) O[mt][j][c] = 0.f;
    float ls[2][2] = {{0.f, 0.f}, {0.f, 0.f}};

    const int krow = (lane & 7) + ((lane & 16) ? 8 : 0);
    const int kcb  = (lane & 8) ? 16 : 0;
    const int vrow = (lane & 7) + ((lane & 8) ? 8 : 0);
    const int vcb  = (lane & 16) ? 16 : 0;

    for (int it = 0; it < SEQ / 64; it++) {
        const int cur = it & 1;
        if (it + 1 < SEQ / 64) {
            flash_load_kv(smb, bh, it + 1, cur ^ 1);
            CP_WAIT1();
        } else {
            CP_WAIT0();
        }
        __syncthreads();

        const uint32_t kb = smb + 8192 + cur * 16384;

        // S[32 rows x 32 kv] = Q K^T (log2 domain)
        float S[2][4][4];
#pragma unroll
        for (int mt = 0; mt < 2; mt++)
#pragma unroll
            for (int j = 0; j < 4; j++)
#pragma unroll
                for (int c = 0; c < 4; c++) S[mt][j][c] = 0.f;

#pragma unroll
        for (int k = 0; k < 4; k++) {
            uint32_t kf[2][4];
#pragma unroll
            for (int nt = 0; nt < 2; nt++)
                ldsm4(kf[nt], kb + SWZ((uint32_t)((chb + nt * 16 + krow) * 128 + k * 32 + kcb)));
#pragma unroll
            for (int mt = 0; mt < 2; mt++)
#pragma unroll
                for (int nt = 0; nt < 2; nt++) {
                    mma16816h(S[mt][2 * nt],     qf[mt][k], kf[nt]);
                    mma16816h(S[mt][2 * nt + 1], qf[mt][k], kf[nt] + 2);
                }
        }

        // P = 2^S via ex2.f16x2; row-sum partials in f16x2
        uint32_t pf[2][2][4];
#pragma unroll
        for (int mt = 0; mt < 2; mt++) {
#pragma unroll
            for (int ks = 0; ks < 2; ks++) {
                pf[mt][ks][0] = ex2_h2(pack_h2(S[mt][2 * ks][0],     S[mt][2 * ks][1]));
                pf[mt][ks][1] = ex2_h2(pack_h2(S[mt][2 * ks][2],     S[mt][2 * ks][3]));
                pf[mt][ks][2] = ex2_h2(pack_h2(S[mt][2 * ks + 1][0], S[mt][2 * ks + 1][1]));
                pf[mt][ks][3] = ex2_h2(pack_h2(S[mt][2 * ks + 1][2], S[mt][2 * ks + 1][3]));
            }
            uint32_t h0 = hadd2(hadd2(pf[mt][0][0], pf[mt][0][2]),
                                hadd2(pf[mt][1][0], pf[mt][1][2]));
            uint32_t h1 = hadd2(hadd2(pf[mt][0][1], pf[mt][0][3]),
                                hadd2(pf[mt][1][1], pf[mt][1][3]));
            float2 f0 = __half22float2(*(__half2*)&h0);
            float2 f1 = __half22float2(*(__half2*)&h1);
            ls[mt][0] += f0.x + f0.y;
            ls[mt][1] += f1.x + f1.y;
        }

        // O += P V (partial over this warp's kv half)
#pragma unroll
        for (int ks = 0; ks < 2; ks++) {
#pragma unroll
            for (int p = 0; p < 4; p++) {
                uint32_t vf[4];
                ldsm4t(vf, kb + 8192 + SWZ((uint32_t)((chb + ks * 16 + vrow) * 128 + p * 32 + vcb)));
#pragma unroll
                for (int mt = 0; mt < 2; mt++) {
                    mma16816h(O[mt][2 * p],     pf[mt][ks], vf);
                    mma16816h(O[mt][2 * p + 1], pf[mt][ks], vf + 2);
                }
            }
        }
        __syncthreads();
    }

    // ---- epilogue: reduce O/lsum across kv halves (ch), normalize, store ----
#pragma unroll
    for (int mt = 0; mt < 2; mt++)
#pragma unroll
        for (int hh = 0; hh < 2; hh++) {
            ls[mt][hh] += __shfl_xor_sync(0xffffffffu, ls[mt][hh], 1);
            ls[mt][hh] += __shfl_xor_sync(0xffffffffu, ls[mt][hh], 2);
        }

    float* Ls = (float*)sm_f;              // [64]
    float* Os = (float*)(sm_f + 1024);     // [64][68] fp32 = 17408B

    if (ch == 1) {
        if ((lane & 3) == 0) {
#pragma unroll
            for (int mt = 0; mt < 2; mt++) {
                Ls[m0 + mt * 16 + (lane >> 2)]     = ls[mt][0];
                Ls[m0 + mt * 16 + (lane >> 2) + 8] = ls[mt][1];
            }
        }
#pragma unroll
        for (int mt = 0; mt < 2; mt++) {
            int r = m0 + mt * 16 + (lane >> 2);
#pragma unroll
            for (int j = 0; j < 8; j++) {
                int col = j * 8 + 2 * (lane & 3);
                *(float2*)&Os[r * 68 + col]       = make_float2(O[mt][j][0], O[mt][j][1]);
                *(float2*)&Os[(r + 8) * 68 + col] = make_float2(O[mt][j][2], O[mt][j][3]);
            }
        }
    }
    __syncthreads();

    if (ch == 0) {
        const int b = bh >> 3, h = bh & 7;
#pragma unroll
        for (int mt = 0; mt < 2; mt++) {
            int r = m0 + mt * 16 + (lane >> 2);
            float i0 = 1.f / (ls[mt][0] + Ls[r]);
            float i1 = 1.f / (ls[mt][1] + Ls[r + 8]);
            size_t base0 = ((size_t)(b * SEQ + s0 + r)) * CCH + h * DH + 2 * (lane & 3);
            size_t base1 = base0 + (size_t)8 * CCH;
#pragma unroll
            for (int j = 0; j < 8; j++) {
                int col = j * 8 + 2 * (lane & 3);
                float2 a0 = *(float2*)&Os[r * 68 + col];
                float2 a1 = *(float2*)&Os[(r + 8) * 68 + col];
                *(uint32_t*)(g_Of + base0 + 8 * j) =
                    pack_h2((O[mt][j][0] + a0.x) * i0, (O[mt][j][1] + a0.y) * i0);
                *(uint32_t*)(g_Of + base1 + 8 * j) =
                    pack_h2((O[mt][j][2] + a1.x) * i1, (O[mt][j][3] + a1.y) * i1);
            }
        }
    }
}

// ---------------------------------------------------------------------------
extern "C" void kernel_launch(void* const* d_in, const int* in_sizes, int n_in,
                              void* d_out, int out_size)
{
    const float* x  = (const float*)d_in[0];
    const float* Wq = (const float*)d_in[1];
    const float* bq = (const float*)d_in[2];
    const float* Wk = (const float*)d_in[3];
    const float* bk = (const float*)d_in[4];
    const float* Wv = (const float*)d_in[5];
    const float* bv = (const float*)d_in[6];
    const float* Wp = (const float*)d_in[7];
    const float* bp = (const float*)d_in[8];
    float* out = (float*)d_out;

    prep_kernel<<<8192, 256>>>(Wq, Wk, Wv, Wp, x);
    gemm_qkv<<<dim3(MROWS / 128, CCH / 64, 3), 256>>>(bq, bk, bv);
    flash_mma<<<dim3(SEQ / 64, BH), 128>>>();
    gemm_proj<<<dim3(MROWS / 128, CCH / 64), 256>>>(bp, out);
}